// round 2
// baseline (speedup 1.0000x reference)
#include <cuda_runtime.h>

// Problem constants (MlaNer1): B=64, L=512, H2=1536, T=64
#define K_DIM 1536
#define N_DIM 64
#define BM 256
#define BK 16
#define NTHREADS 256
#define MAX_BLOCKS 512

// Per-block partial reductions (deterministic: tree-reduced, no float atomics)
__device__ float g_partLoss[MAX_BLOCKS];
__device__ int   g_partRight[MAX_BLOCKS];
__device__ int   g_partCount[MAX_BLOCKS];

// Fused kernel: fp32 SIMT GEMM (BM=256 x N=64, BK=16, 8x8 micro-tile,
// double-buffered smem) + per-token softmax-stats epilogue + loss/acc.
__global__ __launch_bounds__(NTHREADS, 1)
void fused_kernel(const float* __restrict__ x,
                  const float* __restrict__ W,
                  const float* __restrict__ bias,
                  const int* __restrict__ tags,      // int32 in harness buffers
                  const float* __restrict__ t2s,
                  const int* __restrict__ tptr,
                  int M)
{
    extern __shared__ float smem[];
    float* sXb[2] = { smem,                smem + BK * BM };
    float* sWb[2] = { smem + 2 * BK * BM,  smem + 2 * BK * BM + BK * N_DIM };

    const int tid = threadIdx.x;
    const int m0  = blockIdx.x * BM;
    const int tm  = tid >> 3;   // 0..31 : 8-row group
    const int tn  = tid & 7;    // 0..7  : 8-col group

    // x row this thread stages (clamped for safety on ragged M)
    int ldrow = m0 + tid;
    if (ldrow >= M) ldrow = M - 1;
    const float* xrow = x + (size_t)ldrow * K_DIM;

    const int wk = tid >> 4;           // 0..15
    const int wn = (tid & 15) << 2;    // 0,4,...,60

    // ---- preload chunk 0 into registers ----
    float4 rx0 = *(const float4*)(xrow + 0);
    float4 rx1 = *(const float4*)(xrow + 4);
    float4 rx2 = *(const float4*)(xrow + 8);
    float4 rx3 = *(const float4*)(xrow + 12);
    float4 rw  = *(const float4*)(W + (size_t)wk * N_DIM + wn);

    float acc[8][8];
    #pragma unroll
    for (int i = 0; i < 8; i++)
        #pragma unroll
        for (int j = 0; j < 8; j++) acc[i][j] = 0.f;

    const int NCHUNK = K_DIM / BK;  // 96
    int buf = 0;

    for (int c = 0; c < NCHUNK; ++c) {
        float* cx = sXb[buf];
        float* cw = sWb[buf];

        // store staged registers -> smem (sX transposed: sX[k][m], conflict-free)
        cx[ 0 * BM + tid] = rx0.x; cx[ 1 * BM + tid] = rx0.y;
        cx[ 2 * BM + tid] = rx0.z; cx[ 3 * BM + tid] = rx0.w;
        cx[ 4 * BM + tid] = rx1.x; cx[ 5 * BM + tid] = rx1.y;
        cx[ 6 * BM + tid] = rx1.z; cx[ 7 * BM + tid] = rx1.w;
        cx[ 8 * BM + tid] = rx2.x; cx[ 9 * BM + tid] = rx2.y;
        cx[10 * BM + tid] = rx2.z; cx[11 * BM + tid] = rx2.w;
        cx[12 * BM + tid] = rx3.x; cx[13 * BM + tid] = rx3.y;
        cx[14 * BM + tid] = rx3.z; cx[15 * BM + tid] = rx3.w;
        *(float4*)(cw + wk * N_DIM + wn) = rw;

        __syncthreads();

        // prefetch next chunk (latency hidden under compute below)
        if (c + 1 < NCHUNK) {
            const float* xp = xrow + (c + 1) * BK;
            rx0 = *(const float4*)(xp + 0);
            rx1 = *(const float4*)(xp + 4);
            rx2 = *(const float4*)(xp + 8);
            rx3 = *(const float4*)(xp + 12);
            rw  = *(const float4*)(W + ((size_t)(c + 1) * BK + wk) * N_DIM + wn);
        }

        // compute this chunk
        #pragma unroll
        for (int k = 0; k < BK; k++) {
            float4 a0 = *(const float4*)(cx + k * BM + tm * 8);
            float4 a1 = *(const float4*)(cx + k * BM + tm * 8 + 4);
            float4 w0 = *(const float4*)(cw + k * N_DIM + tn * 8);
            float4 w1 = *(const float4*)(cw + k * N_DIM + tn * 8 + 4);
            float a[8] = {a0.x, a0.y, a0.z, a0.w, a1.x, a1.y, a1.z, a1.w};
            float w[8] = {w0.x, w0.y, w0.z, w0.w, w1.x, w1.y, w1.z, w1.w};
            #pragma unroll
            for (int i = 0; i < 8; i++)
                #pragma unroll
                for (int j = 0; j < 8; j++)
                    acc[i][j] = fmaf(a[i], w[j], acc[i][j]);
        }
        buf ^= 1;
        // single barrier per chunk: next iter's STS targets the other buffer,
        // and its __syncthreads orders reuse of this one.
    }

    // ---- epilogue: per-token softmax stats + loss + accuracy ----
    // Row r's 64 logits live in the 8 consecutive lanes tm*8..tm*8+7 (same warp).
    float bv[8];
    #pragma unroll
    for (int j = 0; j < 8; j++) bv[j] = bias[tn * 8 + j];

    const int   tval = *tptr;                   // exponent t
    const float E1   = 2.718281828459045f;

    float myLoss = 0.f;
    int myRight = 0, myCount = 0;

    #pragma unroll
    for (int r = 0; r < 8; r++) {
        const int grow = m0 + tm * 8 + r;
        float v[8];
        float lmax = -1e30f;
        int   lidx = 0;
        float lsum = 0.f;
        #pragma unroll
        for (int j = 0; j < 8; j++) {
            v[j] = acc[r][j] + bv[j];
            lsum += v[j];
            if (v[j] > lmax) { lmax = v[j]; lidx = tn * 8 + j; }
        }
        // width-8 butterfly all-reduce: max + first-argmax
        #pragma unroll
        for (int o = 1; o < 8; o <<= 1) {
            float om = __shfl_xor_sync(0xffffffffu, lmax, o, 8);
            int   oi = __shfl_xor_sync(0xffffffffu, lidx, o, 8);
            if (om > lmax || (om == lmax && oi < lidx)) { lmax = om; lidx = oi; }
        }
        float z = 0.f;
        #pragma unroll
        for (int j = 0; j < 8; j++) z += __expf(v[j] - lmax);
        #pragma unroll
        for (int o = 1; o < 8; o <<= 1) {
            z    += __shfl_xor_sync(0xffffffffu, z,    o, 8);
            lsum += __shfl_xor_sync(0xffffffffu, lsum, o, 8);
        }

        if (grow < M) {
            const int tg = tags[grow];
            if ((tg >> 3) == tn) {   // this lane owns the tag's column group
                // extract v[tg&7] without dynamic local-mem indexing
                float ltag = v[0];
                #pragma unroll
                for (int j = 1; j < 8; j++) if ((tg & 7) == j) ltag = v[j];

                float logZ   = __logf(z);
                float lp_tag = ltag - lmax - logZ;                 // log softmax at tag
                float S_log  = lsum - 64.f * (lmax + logZ);        // sum_t log p_t
                float s  = t2s[tg];
                float sc = powf(s, (float)tval);
                float es = __expf(sc);
                float Zy = 63.f * E1 + es;
                float y_non = E1 / Zy;
                float y_hot = es / Zy;
                myLoss -= y_non * S_log + (y_hot - y_non) * lp_tag;
                if (tg < N_DIM - 3) { myCount++; if (lidx == tg) myRight++; }
            }
        }
    }

    // ---- deterministic block tree-reduction (reuse smem) ----
    __syncthreads();
    float* rl = smem;
    int*   rr = (int*)(smem + NTHREADS);
    int*   rc = (int*)(smem + 2 * NTHREADS);
    rl[tid] = myLoss; rr[tid] = myRight; rc[tid] = myCount;
    __syncthreads();
    #pragma unroll
    for (int s2 = NTHREADS / 2; s2 > 0; s2 >>= 1) {
        if (tid < s2) {
            rl[tid] += rl[tid + s2];
            rr[tid] += rr[tid + s2];
            rc[tid] += rc[tid + s2];
        }
        __syncthreads();
    }
    if (tid == 0) {
        g_partLoss[blockIdx.x]  = rl[0];
        g_partRight[blockIdx.x] = rr[0];
        g_partCount[blockIdx.x] = rc[0];
    }
}

__global__ void finalize_kernel(float* __restrict__ out, int nb)
{
    __shared__ float sl[256];
    __shared__ int   sr[256];
    __shared__ int   sc[256];
    const int t = threadIdx.x;
    float L = 0.f; int R = 0, C = 0;
    for (int i = t; i < nb; i += 256) {
        L += g_partLoss[i]; R += g_partRight[i]; C += g_partCount[i];
    }
    sl[t] = L; sr[t] = R; sc[t] = C;
    __syncthreads();
    for (int s = 128; s > 0; s >>= 1) {
        if (t < s) { sl[t] += sl[t + s]; sr[t] += sr[t + s]; sc[t] += sc[t + s]; }
        __syncthreads();
    }
    if (t == 0) {
        out[0] = sl[0];                                   // loss1
        out[1] = (float)sr[0] / (float)sc[0];             // acc1
    }
}

extern "C" void kernel_launch(void* const* d_in, const int* in_sizes, int n_in,
                              void* d_out, int out_size)
{
    // metadata order: x, W, b, tags, attention_mask, tag_to_score, t
    const float* x    = (const float*)d_in[0];
    const float* W    = (const float*)d_in[1];
    const float* b    = (const float*)d_in[2];
    const int*   tags = (const int*)d_in[3];   // harness stores ints as int32
    // d_in[4] = attention_mask: additive constant uniform over softmax axis ->
    // provably no effect on p, argmax, or loss. Ignored.
    const float* t2s  = (const float*)d_in[5];
    const int*   tptr = (const int*)d_in[6];

    const int M = in_sizes[3];                 // B*L tokens (32768)
    int nblocks = (M + BM - 1) / BM;           // 128
    if (nblocks > MAX_BLOCKS) nblocks = MAX_BLOCKS;

    const size_t smem_bytes = (size_t)(2 * BK * BM + 2 * BK * N_DIM) * sizeof(float); // 40 KB

    fused_kernel<<<nblocks, NTHREADS, smem_bytes>>>(x, W, b, tags, t2s, tptr, M);
    finalize_kernel<<<1, 256>>>((float*)d_out, nblocks);
}